// round 3
// baseline (speedup 1.0000x reference)
#include <cuda_runtime.h>

#define COLS 8192
#define GROUPS 32
#define ROWS 1024
#define SCALE 0.75f

#define NCHUNK 4
#define CHUNK_COLS (COLS / NCHUNK)        // 2048 cols per chunk
#define RPB 8                             // rows per block
#define NRG (ROWS / RPB)                  // 128 row groups

// Scratch (no allocation allowed).
__device__ float g_wtotal[COLS];
__device__ float g_partial[NCHUNK][ROWS];

// Kernel 1: w_total[c] = sum_g wsums[g][c]
__global__ __launch_bounds__(256) void reduce_w_kernel(const float* __restrict__ wsums) {
    const int colbase = blockIdx.x * 64;
    const int lcol  = threadIdx.x & 63;
    const int chunk = threadIdx.x >> 6;          // 0..3
    const int col   = colbase + lcol;

    float s = 0.0f;
#pragma unroll
    for (int g = 0; g < 8; ++g) {
        s += wsums[(chunk * 8 + g) * COLS + col];
    }

    __shared__ float sm[4][64];
    sm[chunk][lcol] = s;
    __syncthreads();

    if (threadIdx.x < 64) {
        g_wtotal[col] = sm[0][lcol] + sm[1][lcol] + sm[2][lcol] + sm[3][lcol];
    }
}

// Kernel 2: tiled matvec. Block = (column chunk, row group of 8 rows).
// w chunk is loaded ONCE into registers; 8 rows of x are streamed with
// 16 independent LDG.128 per thread across the block lifetime.
__global__ __launch_bounds__(256, 4) void dot_tile_kernel(const float* __restrict__ x) {
    const int chunk = blockIdx.x & (NCHUNK - 1);   // 0..3
    const int rg    = blockIdx.x >> 2;             // 0..127
    const int t     = threadIdx.x;

    // w chunk: thread t owns cols chunk*2048 + t*8 .. +7 (2 float4s)
    const float4* __restrict__ w4 =
        reinterpret_cast<const float4*>(g_wtotal) + chunk * (CHUNK_COLS / 4);
    const float4 w0 = w4[t * 2 + 0];
    const float4 w1 = w4[t * 2 + 1];

    const float4* __restrict__ x4 = reinterpret_cast<const float4*>(x);

    float partial[RPB];
#pragma unroll
    for (int r = 0; r < RPB; ++r) {
        const size_t base = (size_t)(rg * RPB + r) * (COLS / 4)
                          + chunk * (CHUNK_COLS / 4) + t * 2;
        const float4 a0 = x4[base + 0];
        const float4 a1 = x4[base + 1];
        float p = a0.x * w0.x;
        p = fmaf(a0.y, w0.y, p);
        p = fmaf(a0.z, w0.z, p);
        p = fmaf(a0.w, w0.w, p);
        p = fmaf(a1.x, w1.x, p);
        p = fmaf(a1.y, w1.y, p);
        p = fmaf(a1.z, w1.z, p);
        p = fmaf(a1.w, w1.w, p);
        partial[r] = p;
    }

    // Block reduce: 8 rows in parallel, one warp per row.
    __shared__ float sm[RPB][256];
#pragma unroll
    for (int r = 0; r < RPB; ++r) sm[r][t] = partial[r];
    __syncthreads();

    const int wid = t >> 5;      // warp wid reduces row wid
    const int lid = t & 31;
    const float4* smr = reinterpret_cast<const float4*>(sm[wid]);
    const float4 v0 = smr[lid * 2 + 0];
    const float4 v1 = smr[lid * 2 + 1];
    float s = ((v0.x + v0.y) + (v0.z + v0.w)) + ((v1.x + v1.y) + (v1.z + v1.w));
#pragma unroll
    for (int o = 16; o > 0; o >>= 1)
        s += __shfl_xor_sync(0xFFFFFFFFu, s, o);

    if (lid == 0) g_partial[chunk][rg * RPB + wid] = s;
}

// Kernel 3: out[row] = SCALE * sum_chunk partial[chunk][row]
__global__ void combine_kernel(float* __restrict__ out) {
    const int row = blockIdx.x * 256 + threadIdx.x;
    out[row] = SCALE * ((g_partial[0][row] + g_partial[1][row])
                      + (g_partial[2][row] + g_partial[3][row]));
}

extern "C" void kernel_launch(void* const* d_in, const int* in_sizes, int n_in,
                              void* d_out, int out_size) {
    const float* x     = (const float*)d_in[0];  // [1024, 8192] f32
    const float* wsums = (const float*)d_in[1];  // [32, 8192] f32
    float* out         = (float*)d_out;          // [1024, 1] f32

    reduce_w_kernel<<<COLS / 64, 256>>>(wsums);
    dot_tile_kernel<<<NCHUNK * NRG, 256>>>(x);
    combine_kernel<<<ROWS / 256, 256>>>(out);
}

// round 5
// speedup vs baseline: 1.4034x; 1.4034x over previous
#include <cuda_runtime.h>

#define COLS 8192
#define COLS4 2048            // float4 per row
#define GROUPS 32
#define ROWS 1024
#define SCALE 0.75f
#define RPB 4                 // rows per block
#define NBLK (ROWS / RPB)     // 256 blocks

// Scratch (no allocation allowed). 32B-aligned for LDG.256.
__device__ __align__(32) float g_wtotal[COLS];

// 256-bit load (LDG.256) with L2 evict_last: keeps the 32MB x stream L2-resident
// across graph replays, and halves L1tex wavefronts vs LDG.128.
__device__ __forceinline__ void ldg256_el(const float* p, float4& a, float4& b) {
    unsigned r0, r1, r2, r3, r4, r5, r6, r7;
    asm("ld.global.nc.L2::evict_last.v8.b32 {%0,%1,%2,%3,%4,%5,%6,%7}, [%8];"
        : "=r"(r0), "=r"(r1), "=r"(r2), "=r"(r3),
          "=r"(r4), "=r"(r5), "=r"(r6), "=r"(r7)
        : "l"(p));
    a.x = __uint_as_float(r0); a.y = __uint_as_float(r1);
    a.z = __uint_as_float(r2); a.w = __uint_as_float(r3);
    b.x = __uint_as_float(r4); b.y = __uint_as_float(r5);
    b.z = __uint_as_float(r6); b.w = __uint_as_float(r7);
}

// Kernel 1: w_total[c] = sum_g wsums[g][c]. Grid 64 x 256 threads.
// Block owns 32 float4 columns; thread (chunk=t>>5, lcol=t&31) sums 4 groups
// (4 independent coalesced LDG.128), smem combine of the 8 chunks.
__global__ __launch_bounds__(256) void reduce_w_kernel(const float* __restrict__ wsums) {
    const int lcol  = threadIdx.x & 31;
    const int chunk = threadIdx.x >> 5;               // 0..7 (4 groups each)
    const int c4    = blockIdx.x * 32 + lcol;

    const float4* __restrict__ w4 = reinterpret_cast<const float4*>(wsums);
    float4 s = make_float4(0.f, 0.f, 0.f, 0.f);
#pragma unroll
    for (int g = 0; g < 4; ++g) {
        float4 v = w4[(size_t)(chunk * 4 + g) * COLS4 + c4];
        s.x += v.x; s.y += v.y; s.z += v.z; s.w += v.w;
    }

    __shared__ float4 sm[8][32];
    sm[chunk][lcol] = s;
    __syncthreads();

    if (threadIdx.x < 32) {
        float4 r = make_float4(0.f, 0.f, 0.f, 0.f);
#pragma unroll
        for (int c = 0; c < 8; ++c) {
            float4 v = sm[c][threadIdx.x];
            r.x += v.x; r.y += v.y; r.z += v.z; r.w += v.w;
        }
        reinterpret_cast<float4*>(g_wtotal)[c4] = r;
    }
}

// Kernel 2: 4 rows per block. w chunk (128B/thread) lives in registers, loaded
// once per block via LDG.256 from L2. Each row: 4 independent LDG.256 batched,
// then 32 FMAs through 2 accumulators.
__global__ __launch_bounds__(256, 2) void dot4_kernel(const float* __restrict__ x,
                                                      float* __restrict__ out) {
    const int t = threadIdx.x;
    const int row0 = blockIdx.x * RPB;

    // w: thread t owns 32B chunks {i*256+t}, i=0..3  (total 32KB across block)
    float4 w[8];
#pragma unroll
    for (int i = 0; i < 4; ++i)
        ldg256_el(g_wtotal + (size_t)(i * 256 + t) * 8, w[2 * i], w[2 * i + 1]);

    const float* __restrict__ xbase = x + (size_t)row0 * COLS;

    float s[RPB];
#pragma unroll
    for (int r = 0; r < RPB; ++r) {
        const float* __restrict__ xr = xbase + r * COLS;
        float4 a[8];
#pragma unroll
        for (int i = 0; i < 4; ++i)
            ldg256_el(xr + (size_t)(i * 256 + t) * 8, a[2 * i], a[2 * i + 1]);

        float p0 = 0.f, p1 = 0.f;
#pragma unroll
        for (int i = 0; i < 8; i += 2) {
            p0 = fmaf(a[i].x,     w[i].x,     p0);
            p0 = fmaf(a[i].y,     w[i].y,     p0);
            p0 = fmaf(a[i].z,     w[i].z,     p0);
            p0 = fmaf(a[i].w,     w[i].w,     p0);
            p1 = fmaf(a[i + 1].x, w[i + 1].x, p1);
            p1 = fmaf(a[i + 1].y, w[i + 1].y, p1);
            p1 = fmaf(a[i + 1].z, w[i + 1].z, p1);
            p1 = fmaf(a[i + 1].w, w[i + 1].w, p1);
        }
        s[r] = p0 + p1;
    }

    // Reduce all 4 rows: warp shuffles, then warp 0 finishes.
#pragma unroll
    for (int o = 16; o > 0; o >>= 1) {
#pragma unroll
        for (int r = 0; r < RPB; ++r)
            s[r] += __shfl_xor_sync(0xFFFFFFFFu, s[r], o);
    }

    __shared__ float red[RPB][8];
    const int wid = t >> 5, lid = t & 31;
    if (lid == 0) {
#pragma unroll
        for (int r = 0; r < RPB; ++r) red[r][wid] = s[r];
    }
    __syncthreads();

    if (t < 32) {
        const int r = t >> 3, w8 = t & 7;
        float v = red[r][w8];
#pragma unroll
        for (int o = 4; o > 0; o >>= 1)
            v += __shfl_xor_sync(0xFFFFFFFFu, v, o);
        if (w8 == 0) out[row0 + r] = v * SCALE;
    }
}

extern "C" void kernel_launch(void* const* d_in, const int* in_sizes, int n_in,
                              void* d_out, int out_size) {
    const float* x     = (const float*)d_in[0];  // [1024, 8192] f32
    const float* wsums = (const float*)d_in[1];  // [32, 8192] f32
    float* out         = (float*)d_out;          // [1024, 1] f32

    reduce_w_kernel<<<COLS4 / 32, 256>>>(wsums);
    dot4_kernel<<<NBLK, 256>>>(x, out);
}